// round 1
// baseline (speedup 1.0000x reference)
#include <cuda_runtime.h>
#include <math.h>

#define TT 150
#define BB 64
#define DD 2000
#define SS 3000
#define EE 100000

// ---------------- scratch (__device__ globals; re-initialized every call) ----
__device__ float g_Pt[(size_t)TT * DD * BB];   // exp(input) transposed to [T][D][B]
__device__ float g_A[2][SS * BB];              // ping-pong normalized forward scores
__device__ float g_csum[(TT + 1) * BB];        // s_t[b] = sum_s A_t[s,b]
__device__ int   g_cnt[SS];
__device__ int   g_rowptr[SS + 1];
__device__ int   g_cursor[SS];
__device__ int2  g_fp[EE];                     // {from*B, pdf*B} per arc, CSR order by to_state
__device__ float g_ew[EE];                     // exp(trans_logw) in CSR order

// ---------------- precompute: exp + transpose input [T][B][D] -> [T][D][B] ---
__global__ void k_exp_T(const float* __restrict__ in) {
    __shared__ float tile[32][33];
    int t  = blockIdx.z;
    int d0 = blockIdx.x * 32;
    int b0 = blockIdx.y * 32;
    int tx = threadIdx.x, ty = threadIdx.y;
    int d = d0 + tx, b = b0 + ty;
    float v = 0.0f;
    if (d < DD) v = in[((size_t)t * BB + b) * DD + d];
    tile[ty][tx] = __expf(v);
    __syncthreads();
    int dd = d0 + ty, bb = b0 + tx;
    if (dd < DD) g_Pt[((size_t)t * DD + dd) * BB + bb] = tile[tx][ty];
}

// ---------------- init: zero counters/csum, A0 = exp(init_logp) -------------
__global__ void k_init(const float* __restrict__ init_logp) {
    int i = blockIdx.x * blockDim.x + threadIdx.x;
    if (i < SS) { g_cnt[i] = 0; g_cursor[i] = 0; }
    if (i < (TT + 1) * BB) g_csum[i] = 0.0f;
    if (i < SS * BB) {
        int s = i >> 6;
        g_A[0][i] = __expf(init_logp[s]);
    }
}

__global__ void k_hist(const int* __restrict__ to_state) {
    int i = blockIdx.x * blockDim.x + threadIdx.x;
    if (i < EE) atomicAdd(&g_cnt[to_state[i]], 1);
}

// single-block exclusive scan of g_cnt -> g_rowptr; also csum[0][b]
__global__ void k_scan(const float* __restrict__ init_logp) {
    __shared__ int sh[1024];
    __shared__ float shf[1024];
    int tid = threadIdx.x;
    const int CH = 3;                       // 1024*3 >= 3000
    int base_i = tid * CH;
    int local[CH];
    int sum = 0;
    #pragma unroll
    for (int j = 0; j < CH; j++) {
        int idx = base_i + j;
        int v = (idx < SS) ? g_cnt[idx] : 0;
        local[j] = sum;
        sum += v;
    }
    sh[tid] = sum;
    __syncthreads();
    // Kogge-Stone inclusive scan
    for (int off = 1; off < 1024; off <<= 1) {
        int v = (tid >= off) ? sh[tid - off] : 0;
        __syncthreads();
        sh[tid] += v;
        __syncthreads();
    }
    int excl = sh[tid] - sum;               // exclusive prefix for this chunk
    #pragma unroll
    for (int j = 0; j < CH; j++) {
        int idx = base_i + j;
        if (idx < SS) g_rowptr[idx] = excl + local[j];
    }
    if (tid == 0) g_rowptr[SS] = EE;

    // csum[0][b] = sum_s exp(init_logp[s])  (same for every b)
    float fs = 0.0f;
    for (int idx = tid; idx < SS; idx += 1024) fs += __expf(init_logp[idx]);
    shf[tid] = fs;
    __syncthreads();
    for (int off = 512; off > 0; off >>= 1) {
        if (tid < off) shf[tid] += shf[tid + off];
        __syncthreads();
    }
    if (tid < BB) g_csum[tid] = shf[0];
}

__global__ void k_scatter(const int* __restrict__ to_state,
                          const int* __restrict__ from_state,
                          const int* __restrict__ pdf_id,
                          const float* __restrict__ trans_logw) {
    int i = blockIdx.x * blockDim.x + threadIdx.x;
    if (i >= EE) return;
    int to = to_state[i];
    int p = g_rowptr[to] + atomicAdd(&g_cursor[to], 1);
    g_fp[p] = make_int2(from_state[i] * BB, pdf_id[i] * BB);
    g_ew[p] = __expf(trans_logw[i]);
}

// ---------------- main recursion step ---------------------------------------
// block = 256 threads = 4 states x 64 batch; grid = S/4 = 750
__global__ void k_step(int t) {
    const float* __restrict__ Ap = g_A[t & 1];
    float* __restrict__ An = g_A[(t + 1) & 1];
    const float* __restrict__ P = g_Pt + (size_t)t * (DD * BB);

    int tid = threadIdx.x;
    int b  = tid & (BB - 1);
    int sl = tid >> 6;
    int s  = (blockIdx.x << 2) + sl;

    float inv_c = 1.0f / g_csum[t * BB + b];

    int r0 = g_rowptr[s], r1 = g_rowptr[s + 1];
    float acc = 0.0f;
    int e = r0;
    for (; e + 4 <= r1; e += 4) {
        int2 fp0 = g_fp[e], fp1 = g_fp[e + 1], fp2 = g_fp[e + 2], fp3 = g_fp[e + 3];
        float w0 = g_ew[e], w1 = g_ew[e + 1], w2 = g_ew[e + 2], w3 = g_ew[e + 3];
        float a0 = Ap[fp0.x + b], a1 = Ap[fp1.x + b], a2 = Ap[fp2.x + b], a3 = Ap[fp3.x + b];
        float p0 = P[fp0.y + b],  p1 = P[fp1.y + b],  p2 = P[fp2.y + b],  p3 = P[fp3.y + b];
        acc = fmaf(w0 * a0, p0, acc);
        acc = fmaf(w1 * a1, p1, acc);
        acc = fmaf(w2 * a2, p2, acc);
        acc = fmaf(w3 * a3, p3, acc);
    }
    for (; e < r1; e++) {
        int2 fp = g_fp[e];
        acc = fmaf(g_ew[e] * Ap[fp.x + b], P[fp.y + b], acc);
    }
    float val = acc * inv_c;
    An[s * BB + b] = val;

    // per-block partial column sums -> csum[t+1]
    __shared__ float red[256];
    red[tid] = val;
    __syncthreads();
    if (sl == 0) {
        float v = red[b] + red[64 + b] + red[128 + b] + red[192 + b];
        atomicAdd(&g_csum[(t + 1) * BB + b], v);
    }
}

// ---------------- final: objf = sum_b [ log(A_T . F) + sum_t log s_t ] ------
__global__ void k_final(const float* __restrict__ final_logp, float* __restrict__ out) {
    __shared__ float red[256];
    const float* At = g_A[TT & 1];
    int b = threadIdx.x & 63;
    int c = threadIdx.x >> 6;
    float acc = 0.0f;
    for (int s = c; s < SS; s += 4)
        acc += At[s * BB + b] * expf(final_logp[s]);
    red[threadIdx.x] = acc;
    __syncthreads();
    if (c == 0) {
        float dot = red[b] + red[64 + b] + red[128 + b] + red[192 + b];
        float lg = logf(dot);
        for (int t = 0; t < TT; t++) lg += logf(g_csum[t * BB + b]);
        red[b] = lg;
    }
    __syncthreads();
    if (threadIdx.x == 0) {
        float s = 0.0f;
        for (int bb = 0; bb < BB; bb++) s += red[bb];
        out[0] = s;
    }
}

// ---------------- launch -----------------------------------------------------
extern "C" void kernel_launch(void* const* d_in, const int* in_sizes, int n_in,
                              void* d_out, int out_size) {
    const float* input      = (const float*)d_in[0];
    const float* trans_logw = (const float*)d_in[1];
    const float* init_logp  = (const float*)d_in[2];
    const float* final_logp = (const float*)d_in[3];
    const int*   from_state = (const int*)d_in[4];
    const int*   to_state   = (const int*)d_in[5];
    const int*   pdf_id     = (const int*)d_in[6];
    float* out = (float*)d_out;

    dim3 gT((DD + 31) / 32, BB / 32, TT);
    k_exp_T<<<gT, dim3(32, 32)>>>(input);
    k_init<<<(SS * BB + 255) / 256, 256>>>(init_logp);
    k_hist<<<(EE + 255) / 256, 256>>>(to_state);
    k_scan<<<1, 1024>>>(init_logp);
    k_scatter<<<(EE + 255) / 256, 256>>>(to_state, from_state, pdf_id, trans_logw);
    for (int t = 0; t < TT; t++)
        k_step<<<SS / 4, 256>>>(t);
    k_final<<<1, 256>>>(final_logp, out);
}

// round 2
// speedup vs baseline: 1.0152x; 1.0152x over previous
#include <cuda_runtime.h>
#include <math.h>

#define TT 150
#define BB 64
#define DD 2000
#define SS 3000
#define EE 100000
#define STPB 16                    // states per block in k_step (256 thr = 16 states x 16 lanes x float4)

// ---------------- scratch (__device__ globals; re-initialized every call) ----
__device__ float g_Pt[(size_t)TT * DD * BB];   // exp(input) transposed to [T][D][B]
__device__ float g_A[2][SS * BB];              // ping-pong normalized forward scores
__device__ float g_csum[(TT + 1) * BB];        // s_t[b] = sum_s A_t[s,b]
__device__ int   g_cnt[SS];
__device__ int   g_rowptr[SS + 1];
__device__ int   g_cursor[SS];
__device__ int2  g_meta[EE];                   // {from*2048+pdf, ew bits} CSR order by to_state
 
// ---------------- precompute: exp + transpose input [T][B][D] -> [T][D][B] ---
__global__ void k_exp_T(const float* __restrict__ in) {
    __shared__ float tile[32][33];
    int t  = blockIdx.z;
    int d0 = blockIdx.x * 32;
    int b0 = blockIdx.y * 32;
    int tx = threadIdx.x, ty = threadIdx.y;
    int d = d0 + tx, b = b0 + ty;
    float v = 0.0f;
    if (d < DD) v = in[((size_t)t * BB + b) * DD + d];
    tile[ty][tx] = __expf(v);
    __syncthreads();
    int dd = d0 + ty, bb = b0 + tx;
    if (dd < DD) g_Pt[((size_t)t * DD + dd) * BB + bb] = tile[tx][ty];
}

// ---------------- init: zero counters/csum, A0 = exp(init_logp) -------------
__global__ void k_init(const float* __restrict__ init_logp) {
    int i = blockIdx.x * blockDim.x + threadIdx.x;
    if (i < SS) { g_cnt[i] = 0; g_cursor[i] = 0; }
    if (i < (TT + 1) * BB) g_csum[i] = 0.0f;
    if (i < SS * BB) {
        int s = i >> 6;
        g_A[0][i] = __expf(init_logp[s]);
    }
}

__global__ void k_hist(const int* __restrict__ to_state) {
    int i = blockIdx.x * blockDim.x + threadIdx.x;
    if (i < EE) atomicAdd(&g_cnt[to_state[i]], 1);
}

// single-block exclusive scan of g_cnt -> g_rowptr; also csum[0][b]
__global__ void k_scan(const float* __restrict__ init_logp) {
    __shared__ int sh[1024];
    __shared__ float shf[1024];
    int tid = threadIdx.x;
    const int CH = 3;                       // 1024*3 >= 3000
    int base_i = tid * CH;
    int local[CH];
    int sum = 0;
    #pragma unroll
    for (int j = 0; j < CH; j++) {
        int idx = base_i + j;
        int v = (idx < SS) ? g_cnt[idx] : 0;
        local[j] = sum;
        sum += v;
    }
    sh[tid] = sum;
    __syncthreads();
    for (int off = 1; off < 1024; off <<= 1) {
        int v = (tid >= off) ? sh[tid - off] : 0;
        __syncthreads();
        sh[tid] += v;
        __syncthreads();
    }
    int excl = sh[tid] - sum;
    #pragma unroll
    for (int j = 0; j < CH; j++) {
        int idx = base_i + j;
        if (idx < SS) g_rowptr[idx] = excl + local[j];
    }
    if (tid == 0) g_rowptr[SS] = EE;

    float fs = 0.0f;
    for (int idx = tid; idx < SS; idx += 1024) fs += __expf(init_logp[idx]);
    shf[tid] = fs;
    __syncthreads();
    for (int off = 512; off > 0; off >>= 1) {
        if (tid < off) shf[tid] += shf[tid + off];
        __syncthreads();
    }
    if (tid < BB) g_csum[tid] = shf[0];
}

__global__ void k_scatter(const int* __restrict__ to_state,
                          const int* __restrict__ from_state,
                          const int* __restrict__ pdf_id,
                          const float* __restrict__ trans_logw) {
    int i = blockIdx.x * blockDim.x + threadIdx.x;
    if (i >= EE) return;
    int to = to_state[i];
    int p = g_rowptr[to] + atomicAdd(&g_cursor[to], 1);
    int packed = (from_state[i] << 11) | pdf_id[i];     // S<4096 (12b), D<2048 (11b)
    g_meta[p] = make_int2(packed, __float_as_int(__expf(trans_logw[i])));
}

// ---------------- main recursion step ---------------------------------------
// 256 threads = 16 states x 16 lanes; each lane handles 4 batch elems (float4)
__global__ void __launch_bounds__(256) k_step(int t) {
    const float* __restrict__ Ap = g_A[t & 1];
    float* __restrict__ An = g_A[(t + 1) & 1];
    const float* __restrict__ P = g_Pt + (size_t)t * (DD * BB);

    int tid = threadIdx.x;
    int bq = (tid & 15) << 2;                 // batch base: 0,4,...,60
    int sl = tid >> 4;                        // 0..15
    int s  = blockIdx.x * STPB + sl;

    float4 c = *(const float4*)&g_csum[t * BB + bq];
    float4 invc = make_float4(__frcp_rn(c.x), __frcp_rn(c.y),
                              __frcp_rn(c.z), __frcp_rn(c.w));

    int r0 = 0, r1 = 0;
    if (s < SS) { r0 = g_rowptr[s]; r1 = g_rowptr[s + 1]; }

    float4 acc = make_float4(0.f, 0.f, 0.f, 0.f);
    int e = r0;
    for (; e + 2 <= r1; e += 2) {
        int2 m0 = g_meta[e];
        int2 m1 = g_meta[e + 1];
        int fo0 = (m0.x >> 11) << 6, po0 = (m0.x & 2047) << 6;
        int fo1 = (m1.x >> 11) << 6, po1 = (m1.x & 2047) << 6;
        float w0 = __int_as_float(m0.y), w1 = __int_as_float(m1.y);
        float4 a0 = *(const float4*)&Ap[fo0 + bq];
        float4 p0 = *(const float4*)&P[po0 + bq];
        float4 a1 = *(const float4*)&Ap[fo1 + bq];
        float4 p1 = *(const float4*)&P[po1 + bq];
        acc.x = fmaf(w0 * a0.x, p0.x, acc.x);
        acc.y = fmaf(w0 * a0.y, p0.y, acc.y);
        acc.z = fmaf(w0 * a0.z, p0.z, acc.z);
        acc.w = fmaf(w0 * a0.w, p0.w, acc.w);
        acc.x = fmaf(w1 * a1.x, p1.x, acc.x);
        acc.y = fmaf(w1 * a1.y, p1.y, acc.y);
        acc.z = fmaf(w1 * a1.z, p1.z, acc.z);
        acc.w = fmaf(w1 * a1.w, p1.w, acc.w);
    }
    if (e < r1) {
        int2 m = g_meta[e];
        int fo = (m.x >> 11) << 6, po = (m.x & 2047) << 6;
        float w = __int_as_float(m.y);
        float4 a = *(const float4*)&Ap[fo + bq];
        float4 p = *(const float4*)&P[po + bq];
        acc.x = fmaf(w * a.x, p.x, acc.x);
        acc.y = fmaf(w * a.y, p.y, acc.y);
        acc.z = fmaf(w * a.z, p.z, acc.z);
        acc.w = fmaf(w * a.w, p.w, acc.w);
    }

    float4 val = make_float4(acc.x * invc.x, acc.y * invc.y,
                             acc.z * invc.z, acc.w * invc.w);
    if (s < SS) *(float4*)&An[s * BB + bq] = val;

    // block reduction over the 16 states -> csum[t+1][b]
    __shared__ float4 red[256];
    red[tid] = val;
    __syncthreads();
    #pragma unroll
    for (int off = 128; off >= 16; off >>= 1) {
        if (tid < off) {
            float4 o = red[tid + off];
            red[tid].x += o.x; red[tid].y += o.y;
            red[tid].z += o.z; red[tid].w += o.w;
        }
        __syncthreads();
    }
    if (tid < 16) {
        float4 v = red[tid];
        float* dst = &g_csum[(t + 1) * BB + (tid << 2)];
        atomicAdd(dst + 0, v.x);
        atomicAdd(dst + 1, v.y);
        atomicAdd(dst + 2, v.z);
        atomicAdd(dst + 3, v.w);
    }
}

// ---------------- final: objf = sum_b [ log(A_T . F) + sum_t log s_t ] ------
__global__ void k_final(const float* __restrict__ final_logp, float* __restrict__ out) {
    __shared__ float red[256];
    const float* At = g_A[TT & 1];
    int b = threadIdx.x & 63;
    int c = threadIdx.x >> 6;
    float acc = 0.0f;
    for (int s = c; s < SS; s += 4)
        acc += At[s * BB + b] * expf(final_logp[s]);
    red[threadIdx.x] = acc;
    __syncthreads();
    if (c == 0) {
        float dot = red[b] + red[64 + b] + red[128 + b] + red[192 + b];
        float lg = logf(dot);
        for (int t = 0; t < TT; t++) lg += logf(g_csum[t * BB + b]);
        red[b] = lg;
    }
    __syncthreads();
    if (threadIdx.x == 0) {
        float s = 0.0f;
        for (int bb = 0; bb < BB; bb++) s += red[bb];
        out[0] = s;
    }
}

// ---------------- launch -----------------------------------------------------
extern "C" void kernel_launch(void* const* d_in, const int* in_sizes, int n_in,
                              void* d_out, int out_size) {
    const float* input      = (const float*)d_in[0];
    const float* trans_logw = (const float*)d_in[1];
    const float* init_logp  = (const float*)d_in[2];
    const float* final_logp = (const float*)d_in[3];
    const int*   from_state = (const int*)d_in[4];
    const int*   to_state   = (const int*)d_in[5];
    const int*   pdf_id     = (const int*)d_in[6];
    float* out = (float*)d_out;

    dim3 gT((DD + 31) / 32, BB / 32, TT);
    k_exp_T<<<gT, dim3(32, 32)>>>(input);
    k_init<<<(SS * BB + 255) / 256, 256>>>(init_logp);
    k_hist<<<(EE + 255) / 256, 256>>>(to_state);
    k_scan<<<1, 1024>>>(init_logp);
    k_scatter<<<(EE + 255) / 256, 256>>>(to_state, from_state, pdf_id, trans_logw);
    for (int t = 0; t < TT; t++)
        k_step<<<(SS + STPB - 1) / STPB, 256>>>(t);
    k_final<<<1, 256>>>(final_logp, out);
}

// round 3
// speedup vs baseline: 1.2285x; 1.2101x over previous
#include <cuda_runtime.h>
#include <math.h>

#define TT 150
#define BB 64
#define DD 2000
#define SS 3000
#define EE 100000
#define STPB 16
#define NBLK ((SS + STPB - 1) / STPB)   // 188 blocks

// ---------------- scratch (__device__ globals; re-initialized every call) ----
__device__ float g_Pt[(size_t)TT * DD * BB];   // exp(input) transposed to [T][D][B]
__device__ float g_A[2][SS * BB];              // ping-pong normalized forward scores
__device__ float g_csum[(TT + 1) * BB];        // s_t[b] = sum_s A_t[s,b]
__device__ int   g_cnt[SS];
__device__ int   g_rowptr[SS + 1];
__device__ int   g_cursor[SS];
__device__ int2  g_meta[EE];                   // {from<<11|pdf, exp(w) bits} CSR by to_state
__device__ unsigned g_count;
__device__ unsigned g_phase;

// ---------------- precompute: exp + transpose input [T][B][D] -> [T][D][B] ---
__global__ void k_exp_T(const float* __restrict__ in) {
    __shared__ float tile[32][33];
    int t  = blockIdx.z;
    int d0 = blockIdx.x * 32;
    int b0 = blockIdx.y * 32;
    int tx = threadIdx.x, ty = threadIdx.y;
    int d = d0 + tx, b = b0 + ty;
    float v = 0.0f;
    if (d < DD) v = in[((size_t)t * BB + b) * DD + d];
    tile[ty][tx] = __expf(v);
    __syncthreads();
    int dd = d0 + ty, bb = b0 + tx;
    if (dd < DD) g_Pt[((size_t)t * DD + dd) * BB + bb] = tile[tx][ty];
}

// ---------------- init ------------------------------------------------------
__global__ void k_init(const float* __restrict__ init_logp) {
    int i = blockIdx.x * blockDim.x + threadIdx.x;
    if (i == 0) { g_count = 0; g_phase = 0; }
    if (i < SS) { g_cnt[i] = 0; g_cursor[i] = 0; }
    if (i < (TT + 1) * BB) g_csum[i] = 0.0f;
    if (i < SS * BB) {
        int s = i >> 6;
        g_A[0][i] = __expf(init_logp[s]);
    }
}

__global__ void k_hist(const int* __restrict__ to_state) {
    int i = blockIdx.x * blockDim.x + threadIdx.x;
    if (i < EE) atomicAdd(&g_cnt[to_state[i]], 1);
}

// single-block exclusive scan of g_cnt -> g_rowptr; also csum[0][b]
__global__ void k_scan(const float* __restrict__ init_logp) {
    __shared__ int sh[1024];
    __shared__ float shf[1024];
    int tid = threadIdx.x;
    const int CH = 3;
    int base_i = tid * CH;
    int local[CH];
    int sum = 0;
    #pragma unroll
    for (int j = 0; j < CH; j++) {
        int idx = base_i + j;
        int v = (idx < SS) ? g_cnt[idx] : 0;
        local[j] = sum;
        sum += v;
    }
    sh[tid] = sum;
    __syncthreads();
    for (int off = 1; off < 1024; off <<= 1) {
        int v = (tid >= off) ? sh[tid - off] : 0;
        __syncthreads();
        sh[tid] += v;
        __syncthreads();
    }
    int excl = sh[tid] - sum;
    #pragma unroll
    for (int j = 0; j < CH; j++) {
        int idx = base_i + j;
        if (idx < SS) g_rowptr[idx] = excl + local[j];
    }
    if (tid == 0) g_rowptr[SS] = EE;

    float fs = 0.0f;
    for (int idx = tid; idx < SS; idx += 1024) fs += __expf(init_logp[idx]);
    shf[tid] = fs;
    __syncthreads();
    for (int off = 512; off > 0; off >>= 1) {
        if (tid < off) shf[tid] += shf[tid + off];
        __syncthreads();
    }
    if (tid < BB) g_csum[tid] = shf[0];
}

__global__ void k_scatter(const int* __restrict__ to_state,
                          const int* __restrict__ from_state,
                          const int* __restrict__ pdf_id,
                          const float* __restrict__ trans_logw) {
    int i = blockIdx.x * blockDim.x + threadIdx.x;
    if (i >= EE) return;
    int to = to_state[i];
    int p = g_rowptr[to] + atomicAdd(&g_cursor[to], 1);
    int packed = (from_state[i] << 11) | pdf_id[i];
    g_meta[p] = make_int2(packed, __float_as_int(__expf(trans_logw[i])));
}

// ---------------- persistent forward recursion -------------------------------
__device__ __forceinline__ float4 ldcg4(const float* p) {
    return __ldcg((const float4*)p);
}

__global__ void __launch_bounds__(256, 2) k_forward() {
    int tid = threadIdx.x;
    int bq = (tid & 15) << 2;                  // batch base
    int sl = tid >> 4;                         // state slot 0..15
    int s  = blockIdx.x * STPB + sl;

    int r0 = 0, r1 = 0;
    if (s < SS) { r0 = __ldg(&g_rowptr[s]); r1 = __ldg(&g_rowptr[s + 1]); }

    __shared__ float4 red[256];

    for (int t = 0; t < TT; t++) {
        const float* __restrict__ Ap = g_A[t & 1];
        float*       __restrict__ An = g_A[(t + 1) & 1];
        const float* __restrict__ P  = g_Pt + (size_t)t * (DD * BB);

        float4 c = ldcg4(&g_csum[t * BB + bq]);
        float4 invc = make_float4(__frcp_rn(c.x), __frcp_rn(c.y),
                                  __frcp_rn(c.z), __frcp_rn(c.w));

        float4 acc = make_float4(0.f, 0.f, 0.f, 0.f);
        int e = r0;
        for (; e + 4 <= r1; e += 4) {
            int2 m0 = __ldg(&g_meta[e]);
            int2 m1 = __ldg(&g_meta[e + 1]);
            int2 m2 = __ldg(&g_meta[e + 2]);
            int2 m3 = __ldg(&g_meta[e + 3]);
            float4 a0 = ldcg4(&Ap[((m0.x >> 11) << 6) + bq]);
            float4 a1 = ldcg4(&Ap[((m1.x >> 11) << 6) + bq]);
            float4 a2 = ldcg4(&Ap[((m2.x >> 11) << 6) + bq]);
            float4 a3 = ldcg4(&Ap[((m3.x >> 11) << 6) + bq]);
            float4 p0 = *(const float4*)&P[((m0.x & 2047) << 6) + bq];
            float4 p1 = *(const float4*)&P[((m1.x & 2047) << 6) + bq];
            float4 p2 = *(const float4*)&P[((m2.x & 2047) << 6) + bq];
            float4 p3 = *(const float4*)&P[((m3.x & 2047) << 6) + bq];
            float w0 = __int_as_float(m0.y), w1 = __int_as_float(m1.y);
            float w2 = __int_as_float(m2.y), w3 = __int_as_float(m3.y);
            acc.x = fmaf(w0 * a0.x, p0.x, acc.x);
            acc.y = fmaf(w0 * a0.y, p0.y, acc.y);
            acc.z = fmaf(w0 * a0.z, p0.z, acc.z);
            acc.w = fmaf(w0 * a0.w, p0.w, acc.w);
            acc.x = fmaf(w1 * a1.x, p1.x, acc.x);
            acc.y = fmaf(w1 * a1.y, p1.y, acc.y);
            acc.z = fmaf(w1 * a1.z, p1.z, acc.z);
            acc.w = fmaf(w1 * a1.w, p1.w, acc.w);
            acc.x = fmaf(w2 * a2.x, p2.x, acc.x);
            acc.y = fmaf(w2 * a2.y, p2.y, acc.y);
            acc.z = fmaf(w2 * a2.z, p2.z, acc.z);
            acc.w = fmaf(w2 * a2.w, p2.w, acc.w);
            acc.x = fmaf(w3 * a3.x, p3.x, acc.x);
            acc.y = fmaf(w3 * a3.y, p3.y, acc.y);
            acc.z = fmaf(w3 * a3.z, p3.z, acc.z);
            acc.w = fmaf(w3 * a3.w, p3.w, acc.w);
        }
        for (; e < r1; e++) {
            int2 m = __ldg(&g_meta[e]);
            float4 a = ldcg4(&Ap[((m.x >> 11) << 6) + bq]);
            float4 p = *(const float4*)&P[((m.x & 2047) << 6) + bq];
            float w = __int_as_float(m.y);
            acc.x = fmaf(w * a.x, p.x, acc.x);
            acc.y = fmaf(w * a.y, p.y, acc.y);
            acc.z = fmaf(w * a.z, p.z, acc.z);
            acc.w = fmaf(w * a.w, p.w, acc.w);
        }

        float4 val = make_float4(acc.x * invc.x, acc.y * invc.y,
                                 acc.z * invc.z, acc.w * invc.w);
        if (s < SS)
            __stcg((float4*)&An[s * BB + bq], val);

        // block reduction over the 16 states -> csum[t+1][b]
        red[tid] = val;
        __syncthreads();
        #pragma unroll
        for (int off = 128; off >= 16; off >>= 1) {
            if (tid < off) {
                float4 o = red[tid + off];
                red[tid].x += o.x; red[tid].y += o.y;
                red[tid].z += o.z; red[tid].w += o.w;
            }
            __syncthreads();
        }
        if (tid < 16) {
            float4 v = red[tid];
            float* dst = &g_csum[(t + 1) * BB + (tid << 2)];
            atomicAdd(dst + 0, v.x);
            atomicAdd(dst + 1, v.y);
            atomicAdd(dst + 2, v.z);
            atomicAdd(dst + 3, v.w);
        }
        __syncthreads();   // all stores/atomics of this block issued before arrive

        // ---- grid barrier (release/acquire, CG grid.sync pattern) ----
        if (tid == 0) {
            unsigned target = (unsigned)(t + 1);
            unsigned old;
            asm volatile("atom.add.release.gpu.global.u32 %0, [%1], 1;"
                         : "=r"(old) : "l"(&g_count) : "memory");
            if (old == NBLK - 1) {
                g_count = 0;   // safe: all arrived; ordered before release below
                asm volatile("st.release.gpu.global.u32 [%0], %1;"
                             :: "l"(&g_phase), "r"(target) : "memory");
            } else {
                unsigned ph;
                do {
                    asm volatile("ld.acquire.gpu.global.u32 %0, [%1];"
                                 : "=r"(ph) : "l"(&g_phase) : "memory");
                    if (ph < target) __nanosleep(32);
                } while (ph < target);
            }
        }
        __syncthreads();
    }
}

// ---------------- final: objf = sum_b [ log(A_T . F) + sum_t log s_t ] ------
__global__ void k_final(const float* __restrict__ final_logp, float* __restrict__ out) {
    __shared__ float red[256];
    const float* At = g_A[TT & 1];
    int b = threadIdx.x & 63;
    int c = threadIdx.x >> 6;
    float acc = 0.0f;
    for (int s = c; s < SS; s += 4)
        acc += At[s * BB + b] * expf(final_logp[s]);
    red[threadIdx.x] = acc;
    __syncthreads();
    if (c == 0) {
        float dot = red[b] + red[64 + b] + red[128 + b] + red[192 + b];
        float lg = logf(dot);
        for (int t = 0; t < TT; t++) lg += logf(g_csum[t * BB + b]);
        red[b] = lg;
    }
    __syncthreads();
    if (threadIdx.x == 0) {
        float s = 0.0f;
        for (int bb = 0; bb < BB; bb++) s += red[bb];
        out[0] = s;
    }
}

// ---------------- launch -----------------------------------------------------
extern "C" void kernel_launch(void* const* d_in, const int* in_sizes, int n_in,
                              void* d_out, int out_size) {
    const float* input      = (const float*)d_in[0];
    const float* trans_logw = (const float*)d_in[1];
    const float* init_logp  = (const float*)d_in[2];
    const float* final_logp = (const float*)d_in[3];
    const int*   from_state = (const int*)d_in[4];
    const int*   to_state   = (const int*)d_in[5];
    const int*   pdf_id     = (const int*)d_in[6];
    float* out = (float*)d_out;

    dim3 gT((DD + 31) / 32, BB / 32, TT);
    k_exp_T<<<gT, dim3(32, 32)>>>(input);
    k_init<<<(SS * BB + 255) / 256, 256>>>(init_logp);
    k_hist<<<(EE + 255) / 256, 256>>>(to_state);
    k_scan<<<1, 1024>>>(init_logp);
    k_scatter<<<(EE + 255) / 256, 256>>>(to_state, from_state, pdf_id, trans_logw);
    k_forward<<<NBLK, 256>>>();
    k_final<<<1, 256>>>(final_logp, out);
}